// round 14
// baseline (speedup 1.0000x reference)
#include <cuda_runtime.h>
#include <math.h>

// Problem constants
#define R_    2048
#define C_    1024
#define NCH   8

#define RPB   16                 // rows per block (phase 1)
#define NB    (R_ / RPB)         // 128 blocks
#define NT    512                // threads per block

// Scratch (no allocations allowed -> device globals)
__device__ float g_Lpart[NB * NCH * C_];   // per-block partial log-sums (4MB)
__device__ float g_pA[64 * NB];            // [i][blk] partial sum_r P*s
__device__ float g_pB[64 * NB];            // [i][blk] partial sum_r P
__device__ float g_pSel[NB];               // per-block row-sel partials
__device__ float g_nnz[64];                // reduced nnz_ch_ba
__device__ float g_psum[64];               // reduced sum_r P
__device__ float g_ncolPart[NB];           // per-block colch sums
__device__ float g_selv;                   // reduced row-sel count
__device__ unsigned int g_done;            // barrier arrivals (reset at end)
__device__ unsigned int g_count;           // finalize ticket (reset at end)

// ---------------------------------------------------------------------------
// Single kernel, 128 blocks x 512 threads.
// Phase 1: softmax 1 row/warp (16 rows); stream D tile once (float2/thread,
//          16 accumulators); write Lpart + pA/pB/sel partials.
// Barrier: one atomicAdd arrival per block; warp 0 polls a volatile load.
// Phase 2: block b reduces its 64 outputs over the 128 partials with float4
//          loads (4 per thread); colch = 1-exp; spare warps reduce pA/pB/sel.
// Ticket:  last block writes the 105 scalars, resets counters.
// Output layout: P[131072] | tot[8] | max_nnz[8] | num_col[8] | num_row[8] |
//                nnz_ch_ba[64] | col_density[8] | num_row_sel[1]
// ---------------------------------------------------------------------------
__global__ __launch_bounds__(NT) void k_all(const float* __restrict__ W,
                                            const float* __restrict__ D,
                                            const float* __restrict__ G,
                                            float* __restrict__ out)
{
    __shared__ float sP[RPB][64];
    __shared__ float slq[RPB][NCH];
    __shared__ float sds[RPB][16];
    __shared__ float sSel[RPB];
    __shared__ float sS[RPB];
    __shared__ float4 s4[32][16];          // phase 2 staging (8KB)

    const int t    = threadIdx.x;
    const int wid  = t >> 5;               // 0..15
    const int lane = t & 31;
    const int b    = blockIdx.x;
    const int r0   = b * RPB;

    const float2* W2 = reinterpret_cast<const float2*>(W);
    const float2* G2 = reinterpret_cast<const float2*>(G);

    // ================= Phase 1 =================
    // ---- softmax: one row per warp ----
    {
        const int rl = wid;
        const int r  = r0 + rl;

        float2 w  = W2[r * 32 + lane];
        float2 gv = G2[r * 32 + lane];
        float e0 = w.x + gv.x;
        float e1 = w.y + gv.y;

        float m = fmaxf(e0, e1);
        #pragma unroll
        for (int o = 16; o > 0; o >>= 1)
            m = fmaxf(m, __shfl_xor_sync(0xFFFFFFFFu, m, o));

        float x0 = expf(e0 - m);
        float x1 = expf(e1 - m);
        float s  = x0 + x1;
        #pragma unroll
        for (int o = 16; o > 0; o >>= 1)
            s += __shfl_xor_sync(0xFFFFFFFFu, s, o);

        const float inv = 1.0f / s;        // == max(P): exp(0)=1 at the argmax
        const float p0  = x0 * inv;
        const float p1  = x1 * inv;

        reinterpret_cast<float2*>(out)[r * 32 + lane] = make_float2(p0, p1);
        sP[rl][2 * lane]     = p0;
        sP[rl][2 * lane + 1] = p1;

        float lq = log1pf(-p0) + log1pf(-p1);
        lq += __shfl_xor_sync(0xFFFFFFFFu, lq, 1);
        lq += __shfl_xor_sync(0xFFFFFFFFu, lq, 2);
        if ((lane & 3) == 0) slq[rl][lane >> 2] = lq;
        if (lane == 0) sSel[rl] = (inv > 0.99f) ? 1.0f : 0.0f;
    }
    __syncthreads();

    // ---- stream D tile once; 2 cols per thread (float2) ----
    {
        float accx[NCH], accy[NCH];
        #pragma unroll
        for (int ch = 0; ch < NCH; ch++) { accx[ch] = 0.f; accy[ch] = 0.f; }
        float dsv[RPB];

        const float2* D2 = reinterpret_cast<const float2*>(D);
        #pragma unroll
        for (int rl = 0; rl < RPB; rl++) {
            float2 d = D2[(size_t)(r0 + rl) * 512 + t];
            dsv[rl] = d.x + d.y;
            #pragma unroll
            for (int ch = 0; ch < NCH; ch++) {
                float l = slq[rl][ch];
                accx[ch] = fmaf(d.x, l, accx[ch]);
                accy[ch] = fmaf(d.y, l, accy[ch]);
            }
        }
        #pragma unroll
        for (int rl = 0; rl < RPB; rl++) {
            float v = dsv[rl];
            #pragma unroll
            for (int o = 16; o > 0; o >>= 1)
                v += __shfl_xor_sync(0xFFFFFFFFu, v, o);
            if (lane == 0) sds[rl][wid] = v;
        }

        #pragma unroll
        for (int ch = 0; ch < NCH; ch++) {
            *reinterpret_cast<float2*>(
                &g_Lpart[((size_t)b * NCH + ch) * C_ + 2 * t]) =
                make_float2(accx[ch], accy[ch]);
        }
    }
    __syncthreads();

    if (t < RPB) {
        float v = 0.f;
        #pragma unroll
        for (int w2 = 0; w2 < 16; w2++) v += sds[t][w2];
        sS[t] = v;
    }
    __syncthreads();

    if (t < 64) {
        float a = 0.f, bb = 0.f;
        #pragma unroll
        for (int rl = 0; rl < RPB; rl++) {
            float p = sP[rl][t];
            bb += p;
            a   = fmaf(p, sS[rl], a);
        }
        g_pA[t * NB + b] = a;
        g_pB[t * NB + b] = bb;
    }
    if (t == 0) {
        float v = 0.f;
        #pragma unroll
        for (int rl = 0; rl < RPB; rl++) v += sSel[rl];
        g_pSel[b] = v;
    }

    // ================= Barrier (no RMW polling) =================
    __syncthreads();
    if (t == 0) { __threadfence(); atomicAdd(&g_done, 1u); }
    if (t < 32) {
        while (*(volatile unsigned int*)&g_done < NB) { }
    }
    __syncthreads();
    __threadfence();   // acquire all blocks' Lpart/pA/pB/sel writes

    // ================= Phase 2 =================
    {
        // block b owns outputs o4 in [b*16, b*16+16) (float4 quads, one ch).
        // thread (q = t&15, pg = t>>4 in 0..31): sums 4 of 128 partials.
        const int q  = t & 15;
        const int pg = t >> 4;             // 0..31
        const float4* Lp4 = reinterpret_cast<const float4*>(g_Lpart);
        const int o4 = b * 16 + q;
        float4 s = make_float4(0.f, 0.f, 0.f, 0.f);
        #pragma unroll
        for (int j = 0; j < 4; j++) {
            float4 v = Lp4[(size_t)(pg * 4 + j) * 2048 + o4];
            s.x += v.x; s.y += v.y; s.z += v.z; s.w += v.w;
        }
        s4[pg][q] = s;
        __syncthreads();

        __shared__ float cs[2];
        if (t < 64) {
            const int ql = t >> 2, comp = t & 3;
            float L = 0.f;
            #pragma unroll
            for (int k = 0; k < 32; k++)
                L += reinterpret_cast<const float*>(&s4[k][ql])[comp];
            float colch = 1.0f - expf(L);
            #pragma unroll
            for (int o = 16; o > 0; o >>= 1)
                colch += __shfl_xor_sync(0xFFFFFFFFu, colch, o);
            if (lane == 0) cs[t >> 5] = colch;
        }

        // spare warps: reduce pA / pB / sel (coalesced rows of 128)
        if (wid == 8 && b < 64) {
            float a = g_pA[b * NB + lane]      + g_pA[b * NB + lane + 32]
                    + g_pA[b * NB + lane + 64] + g_pA[b * NB + lane + 96];
            #pragma unroll
            for (int o = 16; o > 0; o >>= 1)
                a += __shfl_xor_sync(0xFFFFFFFFu, a, o);
            if (lane == 0) g_nnz[b] = a;
        } else if (wid == 9 && b < 64) {
            float a = g_pB[b * NB + lane]      + g_pB[b * NB + lane + 32]
                    + g_pB[b * NB + lane + 64] + g_pB[b * NB + lane + 96];
            #pragma unroll
            for (int o = 16; o > 0; o >>= 1)
                a += __shfl_xor_sync(0xFFFFFFFFu, a, o);
            if (lane == 0) g_psum[b] = a;
        } else if (wid == 10 && b == 64) {
            float a = g_pSel[lane]      + g_pSel[lane + 32]
                    + g_pSel[lane + 64] + g_pSel[lane + 96];
            #pragma unroll
            for (int o = 16; o > 0; o >>= 1)
                a += __shfl_xor_sync(0xFFFFFFFFu, a, o);
            if (lane == 0) g_selv = a;
        }
        __syncthreads();
        if (t == 0) g_ncolPart[b] = cs[0] + cs[1];
    }

    // ================= Ticket finalize =================
    __shared__ int isLast;
    __threadfence();
    if (t == 0) {
        unsigned int old = atomicAdd(&g_count, 1u);
        isLast = (old == NB - 1) ? 1 : 0;
        if (isLast) { g_count = 0; g_done = 0; }   // reset for next replay
    }
    __syncthreads();
    if (!isLast) return;
    __threadfence();                                // acquire phase-2 writes

    if (t < 64) out[131104 + t] = g_nnz[t];         // nnz_ch_ba

    if (t < NCH) {
        float m = -1e30f, ns = 0.f, rs = 0.f;
        #pragma unroll
        for (int ba = 0; ba < 8; ba++) {
            float nv = g_nnz[t * 8 + ba];
            m  = fmaxf(m, nv);
            ns += nv;
            rs += g_psum[t * 8 + ba];
        }
        float ncl = 0.f;
        #pragma unroll
        for (int k = 0; k < 16; k++) ncl += g_ncolPart[t * 16 + k];
        out[131072 + t] = m + ncl + rs;             // tot_ch
        out[131080 + t] = m;                        // max_nnz_ch
        out[131088 + t] = ncl;                      // num_col_ch
        out[131096 + t] = rs;                       // num_row_ch
        out[131168 + t] = ns / rs / ncl;            // col_density_ch
    }
    if (t == 64) out[131176] = g_selv;              // num_row_sel
}

// ---------------------------------------------------------------------------
extern "C" void kernel_launch(void* const* d_in, const int* in_sizes, int n_in,
                              void* d_out, int out_size)
{
    const float* W = (const float*)d_in[0];   // [2048, 64]
    const float* D = (const float*)d_in[1];   // [2048, 1024]
    const float* G = (const float*)d_in[2];   // [2048, 64]
    // d_in[3] = i, unused by the math
    float* out = (float*)d_out;

    k_all<<<NB, NT>>>(W, D, G, out);
}